// round 2
// baseline (speedup 1.0000x reference)
#include <cuda_runtime.h>
#include <math.h>

#define BI 128
#define BT 128
#define RR 36
#define WW 50
#define DD 256
#define KC 64
#define KCP 68          // K-chunk row pad (floats): 272B rows, 16B-aligned, odd bank stride
#define WP 53           // Sinkhorn row pad: coprime with 32 -> conflict-free column sums
#define NTHREADS 256

// Scratch (allocation-free rule: __device__ globals)
__device__ __align__(16) float g_nimg[BI * RR * DD];   // 4.7 MB, L2-resident
__device__ __align__(16) float g_ncap[BT * WW * DD];   // 6.5 MB, L2-resident

// ---------------------------------------------------------------------------
// Kernel 1: L2-normalize each 256-dim row. One warp per row.
// ---------------------------------------------------------------------------
__global__ __launch_bounds__(256)
void norm_kernel(const float* __restrict__ imgs,
                 const float* __restrict__ caps) {
    int gw   = blockIdx.x * (blockDim.x >> 5) + (threadIdx.x >> 5);
    int lane = threadIdx.x & 31;
    const int nimg_rows = BI * RR;   // 4608
    const int ncap_rows = BT * WW;   // 6400
    const float* src;
    float* dst;
    if (gw < nimg_rows) {
        src = imgs + (size_t)gw * DD;
        dst = g_nimg + (size_t)gw * DD;
    } else {
        int g2 = gw - nimg_rows;
        if (g2 >= ncap_rows) return;
        src = caps + (size_t)g2 * DD;
        dst = g_ncap + (size_t)g2 * DD;
    }
    float4 x0 = ((const float4*)src)[lane];
    float4 x1 = ((const float4*)src)[lane + 32];
    float ss = x0.x * x0.x + x0.y * x0.y + x0.z * x0.z + x0.w * x0.w
             + x1.x * x1.x + x1.y * x1.y + x1.z * x1.z + x1.w * x1.w;
#pragma unroll
    for (int o = 16; o; o >>= 1) ss += __shfl_xor_sync(0xffffffffu, ss, o);
    float sc = 1.0f / fmaxf(sqrtf(ss), 1e-8f);
    x0.x *= sc; x0.y *= sc; x0.z *= sc; x0.w *= sc;
    x1.x *= sc; x1.y *= sc; x1.z *= sc; x1.w *= sc;
    ((float4*)dst)[lane]      = x0;
    ((float4*)dst)[lane + 32] = x1;
}

// ---------------------------------------------------------------------------
// Block-wide sum (256 threads = 8 warps)
// ---------------------------------------------------------------------------
__device__ __forceinline__ float block_sum(float v, volatile float* red, int tid) {
#pragma unroll
    for (int o = 16; o; o >>= 1) v += __shfl_xor_sync(0xffffffffu, v, o);
    if ((tid & 31) == 0) red[tid >> 5] = v;
    __syncthreads();
    if (tid < 32) {
        float x = (tid < (NTHREADS >> 5)) ? red[tid] : 0.0f;
#pragma unroll
        for (int o = 4; o; o >>= 1) x += __shfl_xor_sync(0xffffffffu, x, o);
        if (tid == 0) red[32] = x;
    }
    __syncthreads();
    return red[32];
}

// ---------------------------------------------------------------------------
// Kernel 2: one CTA per (i, j) pair.
//   Phase A: S[36][50] = nimg_i @ ncap_j^T  (K=256, fp32 register tiling)
//   Phase B: Sinkhorn (3 iters) + final reduce, all in SMEM.
// Thread map: ty = tid/28 in [0,9), tx = tid%28; thread tile 4 rows x 2 cols
// (cols tx and tx+28; cols 50..55 are zero-padded dead lanes).
// ---------------------------------------------------------------------------
__global__ __launch_bounds__(NTHREADS)
void wass_kernel(const int* __restrict__ ilens, const int* __restrict__ clens,
                 float* __restrict__ out) {
    __shared__ __align__(16) union {
        struct { float As[RR][KCP]; float Bs[56][KCP]; } g;       // ~25 KB
        struct { float S[RR][WP]; float P[RR][WP];
                 float sru[RR]; float scv[WW]; float red[33]; } s; // ~15.7 KB
    } sm;

    const int j   = blockIdx.x;
    const int i   = blockIdx.y;
    const int tid = threadIdx.x;
    const int ty  = tid / 28;      // 0..9 (ty==9 -> compute-idle lanes)
    const int tx  = tid - ty * 28; // 0..27

    const float* Ag = g_nimg + (size_t)i * RR * DD;
    const float* Bg = g_ncap + (size_t)j * WW * DD;

    float acc[4][2] = {{0.f, 0.f}, {0.f, 0.f}, {0.f, 0.f}, {0.f, 0.f}};

    // Zero the B pad rows (50..55) once; never written again.
    for (int t = tid; t < 6 * KCP; t += NTHREADS)
        sm.g.Bs[50 + t / KCP][t % KCP] = 0.0f;

    const int AQ = RR * (KC / 4);   // 576 float4 loads for A tile
    const int BQ = WW * (KC / 4);   // 800 float4 loads for B tile

    for (int kb = 0; kb < DD; kb += KC) {
        __syncthreads();  // previous chunk fully consumed (and pad-zero visible)
        // Unified cooperative tile load: A quads first, then B quads, one stream
        for (int t = tid; t < AQ + BQ; t += NTHREADS) {
            if (t < AQ) {
                int r = t >> 4, kq = t & 15;
                ((float4*)sm.g.As[r])[kq] = ((const float4*)(Ag + r * DD + kb))[kq];
            } else {
                int u = t - AQ;
                int w = u >> 4, kq = u & 15;
                ((float4*)sm.g.Bs[w])[kq] = ((const float4*)(Bg + w * DD + kb))[kq];
            }
        }
        __syncthreads();
        if (ty < 9) {
#pragma unroll
            for (int k = 0; k < KC; k += 4) {
                float4 b0 = *(const float4*)&sm.g.Bs[tx][k];
                float4 b1 = *(const float4*)&sm.g.Bs[tx + 28][k];
#pragma unroll
                for (int rr = 0; rr < 4; rr++) {
                    float4 a = *(const float4*)&sm.g.As[4 * ty + rr][k];
                    acc[rr][0] = fmaf(a.x, b0.x, fmaf(a.y, b0.y,
                                 fmaf(a.z, b0.z, fmaf(a.w, b0.w, acc[rr][0]))));
                    acc[rr][1] = fmaf(a.x, b1.x, fmaf(a.y, b1.y,
                                 fmaf(a.z, b1.z, fmaf(a.w, b1.w, acc[rr][1]))));
                }
            }
        }
    }
    __syncthreads();

    // ---- write S into the aliased Sinkhorn buffer ----
    if (ty < 9) {
#pragma unroll
        for (int rr = 0; rr < 4; rr++) {
            sm.s.S[4 * ty + rr][tx] = acc[rr][0];
            if (tx + 28 < WW) sm.s.S[4 * ty + rr][tx + 28] = acc[rr][1];
        }
    }
    __syncthreads();

    const int nr = ilens[i];
    const int nw = clens[j];

    // P = exp(20*(S-1)) on mask, else 0; accumulate total
    float part = 0.0f;
    for (int idx = tid; idx < RR * WW; idx += NTHREADS) {
        int r = idx / WW, w = idx - r * WW;
        float sv = sm.s.S[r][w];
        float p  = (r < nr && w < nw) ? expf(20.0f * (sv - 1.0f)) : 0.0f;
        sm.s.P[r][w] = p;
        part += p;
    }
    float tot = block_sum(part, sm.s.red, tid);
    float inv = 1.0f / (tot + 1e-6f);
    for (int idx = tid; idx < RR * WW; idx += NTHREADS) {
        int r = idx / WW, w = idx - r * WW;
        sm.s.P[r][w] *= inv;
    }
    __syncthreads();

    // 3 Sinkhorn iterations (match reference: EPS added to raw sums)
#pragma unroll 1
    for (int it = 0; it < 3; it++) {
        if (tid < RR) {
            float u = 0.0f;
#pragma unroll 1
            for (int w = 0; w < WW; w++) u += sm.s.P[tid][w];
            float rm = (tid < nr) ? (1.0f / (float)nr) : 0.0f;
            sm.s.sru[tid] = rm / (u + 1e-6f);
        }
        __syncthreads();
        for (int idx = tid; idx < RR * WW; idx += NTHREADS) {
            int r = idx / WW, w = idx - r * WW;
            sm.s.P[r][w] *= sm.s.sru[r];
        }
        __syncthreads();
        if (tid < WW) {
            float v = 0.0f;
#pragma unroll 1
            for (int r = 0; r < RR; r++) v += sm.s.P[r][tid];
            float cm = (tid < nw) ? (1.0f / (float)nw) : 0.0f;
            sm.s.scv[tid] = cm / (v + 1e-6f);
        }
        __syncthreads();
        for (int idx = tid; idx < RR * WW; idx += NTHREADS) {
            int r = idx / WW, w = idx - r * WW;
            sm.s.P[r][w] *= sm.s.scv[w];
        }
        __syncthreads();
    }

    // sims[i][j] = sum(S * P)
    float fin = 0.0f;
    for (int idx = tid; idx < RR * WW; idx += NTHREADS) {
        int r = idx / WW, w = idx - r * WW;
        fin += sm.s.S[r][w] * sm.s.P[r][w];
    }
    float simv = block_sum(fin, sm.s.red, tid);
    if (tid == 0) out[i * BT + j] = simv;
}

// ---------------------------------------------------------------------------
extern "C" void kernel_launch(void* const* d_in, const int* in_sizes, int n_in,
                              void* d_out, int out_size) {
    const float* imgs  = (const float*)d_in[0];   // [128,36,256] f32
    const float* caps  = (const float*)d_in[1];   // [128,50,256] f32
    const int*   ilens = (const int*)d_in[2];     // [128] i32
    const int*   clens = (const int*)d_in[3];     // [128] i32
    float* out = (float*)d_out;                   // [128,128] f32

    const int total_rows = BI * RR + BT * WW;     // 11008 warps
    int nblocks = (total_rows + 7) / 8;           // 8 warps per 256-thread block
    norm_kernel<<<nblocks, 256>>>(imgs, caps);

    dim3 grid(BT, BI);
    wass_kernel<<<grid, NTHREADS>>>(ilens, clens, out);
}

// round 7
// speedup vs baseline: 1.4313x; 1.4313x over previous
#include <cuda_runtime.h>
#include <cuda_bf16.h>
#include <math.h>
#include <stdint.h>

#define RR 36
#define WW 50
#define DD 256
#define NI 128
#define NJ 128

// ---------------- split bf16 global scratch (allocation-free) --------------
__device__ __align__(16) __nv_bfloat16 g_Ahi[NI * RR * DD];
__device__ __align__(16) __nv_bfloat16 g_Alo[NI * RR * DD];
__device__ __align__(16) __nv_bfloat16 g_Bhi[NJ * WW * DD];
__device__ __align__(16) __nv_bfloat16 g_Blo[NJ * WW * DD];

// ---------------- SMEM layout (bytes) --------------------------------------
// GEMM tiles: 128 rows x 72 bf16 (144B stride; 64 real cols + 8 pad)
#define RS      144
#define TILE_B  (128 * RS)          /* 18432 */
#define ST_AHI  0
#define ST_ALO  (ST_AHI + TILE_B)
#define ST_BHI  (ST_ALO + TILE_B)
#define ST_BLO  (ST_BHI + TILE_B)
#define SMEM_TOTAL (4 * TILE_B)     /* 73728 */
// Sinkhorn region aliases the tiles (used only after GEMM completes)
#define WPAD    53
#define PAIR_F  (RR * WPAD)         /* 1908 floats */
#define SM_P_F  (4 * PAIR_F)        /* float offset of P region = 7632 */

// ---------------- PTX helpers (base-target instructions only) ---------------
__device__ __forceinline__ uint32_t smem_u32(const void* p) {
    uint32_t a;
    asm("{ .reg .u64 t; cvta.to.shared.u64 t, %1; cvt.u32.u64 %0, t; }"
        : "=r"(a) : "l"(p));
    return a;
}
__device__ __forceinline__ void cp16(uint32_t s, const void* g) {
    asm volatile("cp.async.ca.shared.global [%0], [%1], 16;" :: "r"(s), "l"(g));
}
#define CP_COMMIT() asm volatile("cp.async.commit_group;" ::: "memory")
#define CP_WAIT0()  asm volatile("cp.async.wait_group 0;" ::: "memory")

#define LDSM_X4(r, addr)                                                      \
    asm volatile("ldmatrix.sync.aligned.m8n8.x4.shared.b16 {%0,%1,%2,%3}, [%4];" \
                 : "=r"((r)[0]), "=r"((r)[1]), "=r"((r)[2]), "=r"((r)[3])     \
                 : "r"(addr))

#define MMA16816(d, a, b0, b1)                                                \
    asm volatile("mma.sync.aligned.m16n8k16.row.col.f32.bf16.bf16.f32 "       \
                 "{%0,%1,%2,%3}, {%4,%5,%6,%7}, {%8,%9}, {%0,%1,%2,%3};"      \
                 : "+f"((d)[0]), "+f"((d)[1]), "+f"((d)[2]), "+f"((d)[3])     \
                 : "r"((a)[0]), "r"((a)[1]), "r"((a)[2]), "r"((a)[3]),        \
                   "r"(b0), "r"(b1))

// ---------------------------------------------------------------------------
// Prep: L2-normalize each 256-d row, emit split bf16 (hi, lo). 1 warp/row.
// ---------------------------------------------------------------------------
__global__ __launch_bounds__(256)
void prep_kernel(const float* __restrict__ imgs, const float* __restrict__ caps) {
    int gw   = blockIdx.x * 8 + (threadIdx.x >> 5);
    int lane = threadIdx.x & 31;
    const int na = NI * RR;
    const float* src;
    __nv_bfloat16 *dhi, *dlo;
    if (gw < na) {
        src = imgs + (size_t)gw * DD;
        dhi = g_Ahi + (size_t)gw * DD;
        dlo = g_Alo + (size_t)gw * DD;
    } else {
        int g2 = gw - na;
        if (g2 >= NJ * WW) return;
        src = caps + (size_t)g2 * DD;
        dhi = g_Bhi + (size_t)g2 * DD;
        dlo = g_Blo + (size_t)g2 * DD;
    }
    float4 x0 = ((const float4*)src)[lane];
    float4 x1 = ((const float4*)src)[lane + 32];
    float ss = x0.x*x0.x + x0.y*x0.y + x0.z*x0.z + x0.w*x0.w
             + x1.x*x1.x + x1.y*x1.y + x1.z*x1.z + x1.w*x1.w;
#pragma unroll
    for (int o = 16; o; o >>= 1) ss += __shfl_xor_sync(0xffffffffu, ss, o);
    float sc = 1.0f / fmaxf(sqrtf(ss), 1e-8f);
    float xs[8] = { x0.x*sc, x0.y*sc, x0.z*sc, x0.w*sc,
                    x1.x*sc, x1.y*sc, x1.z*sc, x1.w*sc };
#pragma unroll
    for (int h = 0; h < 2; h++) {
        int b = h * 128 + 4 * lane;
#pragma unroll
        for (int q = 0; q < 2; q++) {
            float a = xs[h*4 + q*2], c = xs[h*4 + q*2 + 1];
            __nv_bfloat16 ah = __float2bfloat16(a);
            __nv_bfloat16 ch = __float2bfloat16(c);
            __nv_bfloat16 al = __float2bfloat16(a - __bfloat162float(ah));
            __nv_bfloat16 cl = __float2bfloat16(c - __bfloat162float(ch));
            __nv_bfloat162 hv; hv.x = ah; hv.y = ch;
            __nv_bfloat162 lv; lv.x = al; lv.y = cl;
            ((__nv_bfloat162*)(dhi + b))[q] = hv;
            ((__nv_bfloat162*)(dlo + b))[q] = lv;
        }
    }
}

// ---------------------------------------------------------------------------
// Fused mma.sync GEMM (128x128 tile = 2 imgs x 2 caps) + warp-per-pair Sinkhorn
// 8 warps: wm = wid&1 (m64 block), wn = wid>>1 (n32 block).
// ---------------------------------------------------------------------------
__global__ __launch_bounds__(256, 2)
void wass_mma_kernel(const int* __restrict__ ilens, const int* __restrict__ clens,
                     float* __restrict__ out) {
    extern __shared__ __align__(16) char smem[];
    const uint32_t sb = smem_u32(smem);
    const int tid = threadIdx.x, wid = tid >> 5, lane = tid & 31;
    const int wm = wid & 1, wn = wid >> 1;
    const int i0 = blockIdx.y * 2, j0 = blockIdx.x * 2;

    // ldmatrix per-lane byte offsets (within a tile buffer)
    const uint32_t aoff = (uint32_t)((wm*64 + (lane & 15)) * RS + ((lane >> 4) & 1) * 16);
    const uint32_t boff = (uint32_t)((wn*32 + (lane & 7) + ((lane >> 4) * 8)) * RS
                                     + ((lane >> 3) & 1) * 16);
    const uint32_t a_hi = sb + ST_AHI + aoff, a_lo = sb + ST_ALO + aoff;
    const uint32_t b_hi = sb + ST_BHI + boff, b_lo = sb + ST_BLO + boff;

    float acc[4][4][4];
#pragma unroll
    for (int mb = 0; mb < 4; mb++)
#pragma unroll
        for (int j = 0; j < 4; j++)
#pragma unroll
            for (int e = 0; e < 4; e++) acc[mb][j][e] = 0.0f;

    for (int ch = 0; ch < 4; ch++) {
        const int kb = ch * 64;
        if (ch) __syncthreads();            // prior chunk fully consumed
        // stage chunk: 2048 16B cp.asyncs (A then B, hi+lo together)
        for (int t = tid; t < 2048; t += 256) {
            int u = t & 1023, mr = u >> 3, q = u & 7, r = mr & 63;
            uint32_t soff = (uint32_t)(mr * RS + q * 16);
            if (t < 1024) {
                if (r < RR) {
                    size_t gof = ((size_t)((i0 + (mr >> 6)) * RR + r)) * DD + kb + q * 8;
                    cp16(sb + ST_AHI + soff, g_Ahi + gof);
                    cp16(sb + ST_ALO + soff, g_Alo + gof);
                }
            } else {
                if (r < WW) {
                    size_t gof = ((size_t)((j0 + (mr >> 6)) * WW + r)) * DD + kb + q * 8;
                    cp16(sb + ST_BHI + soff, g_Bhi + gof);
                    cp16(sb + ST_BLO + soff, g_Blo + gof);
                }
            }
        }
        CP_COMMIT(); CP_WAIT0();
        __syncthreads();

#pragma unroll
        for (int ks = 0; ks < 4; ks++) {
            const uint32_t ko = (uint32_t)(ks * 32);
            uint32_t ah[4][4], al[4][4], bb[2][4];
#pragma unroll
            for (int mb = 0; mb < 4; mb++) {
                LDSM_X4(ah[mb], a_hi + (uint32_t)(mb * 16 * RS) + ko);
                LDSM_X4(al[mb], a_lo + (uint32_t)(mb * 16 * RS) + ko);
            }
#pragma unroll
            for (int nb = 0; nb < 2; nb++)
                LDSM_X4(bb[nb], b_hi + (uint32_t)(nb * 16 * RS) + ko);
            // hh + lh (share B-hi)
#pragma unroll
            for (int mb = 0; mb < 4; mb++)
#pragma unroll
                for (int j = 0; j < 4; j++) {
                    MMA16816(acc[mb][j], ah[mb], bb[j >> 1][(j & 1) * 2], bb[j >> 1][(j & 1) * 2 + 1]);
                    MMA16816(acc[mb][j], al[mb], bb[j >> 1][(j & 1) * 2], bb[j >> 1][(j & 1) * 2 + 1]);
                }
            // hl (reload B-lo into bb)
#pragma unroll
            for (int nb = 0; nb < 2; nb++)
                LDSM_X4(bb[nb], b_lo + (uint32_t)(nb * 16 * RS) + ko);
#pragma unroll
            for (int mb = 0; mb < 4; mb++)
#pragma unroll
                for (int j = 0; j < 4; j++)
                    MMA16816(acc[mb][j], ah[mb], bb[j >> 1][(j & 1) * 2], bb[j >> 1][(j & 1) * 2 + 1]);
        }
    }
    __syncthreads();   // all ldmatrix reads done before aliasing S over tiles

    // ---- epilogue: C fragments -> per-pair S blocks (WPAD layout) ----
    {
        float* Sb = (float*)smem;
        const int gr = lane >> 2, tg = lane & 3;
        const int cap = wn >> 1, wbase = (wn & 1) * 32;
#pragma unroll
        for (int mb = 0; mb < 3; mb++) {          // mb=3 -> rows>=48, all masked
#pragma unroll
            for (int j = 0; j < 4; j++) {
                int w0 = wbase + j * 8 + 2 * tg;
#pragma unroll
                for (int e = 0; e < 4; e++) {
                    int r = mb * 16 + gr + ((e >> 1) ? 8 : 0);
                    int w = w0 + (e & 1);
                    if (r < RR && w < WW)
                        Sb[((wm * 2 + cap) * RR + r) * WPAD + w] = acc[mb][j][e];
                }
            }
        }
    }
    __syncthreads();

    // ---- Sinkhorn: warp p handles pair (i0 + (p>>1), j0 + (p&1)) ----
    if (wid < 4) {
        const int i = i0 + (wid >> 1);
        const int j = j0 + (wid & 1);
        const int nr = ilens[i];
        const int nw = clens[j];
        const float invr = 1.0f / (float)nr;
        const float invw = 1.0f / (float)nw;
        float* S = (float*)smem + wid * PAIR_F;
        float* P = (float*)smem + SM_P_F + wid * PAIR_F;
        const int c0 = lane, c1 = lane + 32;
        const bool v1 = (c1 < WW);

        float loc = 0.0f;
#pragma unroll 4
        for (int r = 0; r < RR; r++) {
            float p0 = 0.0f, p1 = 0.0f;
            if (r < nr && c0 < nw) p0 = __expf(20.0f * (S[r * WPAD + c0] - 1.0f));
            P[r * WPAD + c0] = p0;
            if (v1) {
                if (r < nr && c1 < nw) p1 = __expf(20.0f * (S[r * WPAD + c1] - 1.0f));
                P[r * WPAD + c1] = p1;
            }
            loc += p0 + p1;
        }
#pragma unroll
        for (int o = 16; o; o >>= 1) loc += __shfl_xor_sync(0xffffffffu, loc, o);
        float sc = 1.0f / (loc + 1e-6f);
#pragma unroll 4
        for (int r = 0; r < RR; r++) {
            P[r * WPAD + c0] *= sc;
            if (v1) P[r * WPAD + c1] *= sc;
        }

#pragma unroll 1
        for (int it = 0; it < 3; it++) {
#pragma unroll 2
            for (int r = 0; r < RR; r++) {
                float t = P[r * WPAD + c0] + (v1 ? P[r * WPAD + c1] : 0.0f);
#pragma unroll
                for (int o = 16; o; o >>= 1) t += __shfl_xor_sync(0xffffffffu, t, o);
                float f = ((r < nr) ? invr : 0.0f) / (t + 1e-6f);
                P[r * WPAD + c0] *= f;
                if (v1) P[r * WPAD + c1] *= f;
            }
            float v0s = 0.0f, v1s = 0.0f;
#pragma unroll 4
            for (int r = 0; r < RR; r++) {
                v0s += P[r * WPAD + c0];
                if (v1) v1s += P[r * WPAD + c1];
            }
            float f0 = ((c0 < nw) ? invw : 0.0f) / (v0s + 1e-6f);
            float f1 = v1 ? (((c1 < nw) ? invw : 0.0f) / (v1s + 1e-6f)) : 0.0f;
#pragma unroll 4
            for (int r = 0; r < RR; r++) {
                P[r * WPAD + c0] *= f0;
                if (v1) P[r * WPAD + c1] *= f1;
            }
        }

        float fin = 0.0f;
#pragma unroll 4
        for (int r = 0; r < RR; r++) {
            fin += S[r * WPAD + c0] * P[r * WPAD + c0];
            if (v1) fin += S[r * WPAD + c1] * P[r * WPAD + c1];
        }
#pragma unroll
        for (int o = 16; o; o >>= 1) fin += __shfl_xor_sync(0xffffffffu, fin, o);
        if (lane == 0) out[i * NJ + j] = fin;
    }
}

// ---------------------------------------------------------------------------
extern "C" void kernel_launch(void* const* d_in, const int* in_sizes, int n_in,
                              void* d_out, int out_size) {
    const float* imgs  = (const float*)d_in[0];
    const float* caps  = (const float*)d_in[1];
    const int*   ilens = (const int*)d_in[2];
    const int*   clens = (const int*)d_in[3];
    float* out = (float*)d_out;

    cudaFuncSetAttribute(wass_mma_kernel,
                         cudaFuncAttributeMaxDynamicSharedMemorySize, SMEM_TOTAL);

    const int total_rows = NI * RR + NJ * WW;   // 11008 rows, 1 warp each
    int nblocks = (total_rows + 7) / 8;
    prep_kernel<<<nblocks, 256>>>(imgs, caps);

    dim3 grid(NJ / 2, NI / 2);                  // 64 x 64 tiles
    wass_mma_kernel<<<grid, 256, SMEM_TOTAL>>>(ilens, clens, out);
}